// round 16
// baseline (speedup 1.0000x reference)
#include <cuda_runtime.h>
#include <cuda_fp16.h>
#include <math.h>

#define NN 2048
#define TT 20
#define KK 32
#define CC 32
#define OO 64
#define G4 256   // 4*OO

// Scratch (static device globals; no runtime allocation)
__device__ __half2 g_zh[TT * NN * (OO/2)];   // z fp16 (only intermediate)

// NaN-safe fast sigmoid / tanh (rel err ~1e-7, 2 MUFU each)
__device__ __forceinline__ float sigf(float x) {
    return __fdividef(1.0f, 1.0f + __expf(-x));
}
__device__ __forceinline__ float tanhf_fast(float x) {
    return 1.0f - __fdividef(2.0f, __expf(2.0f * x) + 1.0f);
}

// ---------------------------------------------------------------------------
// K1 (tensor-core): z[rows x 64] = x[rows x 32] @ conv_w^T[32 x 64]
// (unchanged from R12)
// ---------------------------------------------------------------------------
__global__ __launch_bounds__(256) void k1_project(const float* __restrict__ x,
                                                  const float* __restrict__ conv_w) {
    __shared__ __half xs[128 * 40];   // 10 KB
    __shared__ __half zs[128 * 72];   // 18 KB staging for z

    const int tid = threadIdx.x;
    const int wid = tid >> 5;
    const int lane = tid & 31;
    const int gid = lane >> 2;
    const int tig = lane & 3;
    const int row0 = blockIdx.x << 7;

    unsigned b[8][2][2];
#pragma unroll
    for (int nt = 0; nt < 8; nt++) {
        const int n0 = (nt << 3) + gid;
        const float* wr = conv_w + n0 * 32;
#pragma unroll
        for (int ks = 0; ks < 2; ks++) {
            const int k0 = (ks << 4) + (tig << 1);
            float2 lo = *(const float2*)(wr + k0);
            float2 hi = *(const float2*)(wr + k0 + 8);
            __half2 p0 = __floats2half2_rn(lo.x, lo.y);
            __half2 p1 = __floats2half2_rn(hi.x, hi.y);
            b[nt][ks][0] = *(unsigned*)&p0;
            b[nt][ks][1] = *(unsigned*)&p1;
        }
    }

    {
        const float4* x4 = (const float4*)x;
#pragma unroll
        for (int it = 0; it < 4; it++) {
            int idx = tid + (it << 8);
            int rl = idx >> 3, c4 = idx & 7;
            int row = row0 + rl;
            int t = row >> 11, n = row & (NN - 1);
            float4 v = x4[((n * TT + t) << 3) + c4];
            *(__half2*)(xs + rl * 40 + (c4 << 2))     = __floats2half2_rn(v.x, v.y);
            *(__half2*)(xs + rl * 40 + (c4 << 2) + 2) = __floats2half2_rn(v.z, v.w);
        }
    }
    __syncthreads();

    const int wbase = wid << 4;
    unsigned a[2][4];
#pragma unroll
    for (int ks = 0; ks < 2; ks++) {
        const int col = (ks << 4) + (tig << 1);
        a[ks][0] = *(const unsigned*)(xs + (wbase + gid) * 40 + col);
        a[ks][1] = *(const unsigned*)(xs + (wbase + gid + 8) * 40 + col);
        a[ks][2] = *(const unsigned*)(xs + (wbase + gid) * 40 + col + 8);
        a[ks][3] = *(const unsigned*)(xs + (wbase + gid + 8) * 40 + col + 8);
    }

#pragma unroll
    for (int nt = 0; nt < 8; nt++) {
        float c0 = 0.f, c1 = 0.f, c2 = 0.f, c3 = 0.f;
#pragma unroll
        for (int ks = 0; ks < 2; ks++) {
            asm volatile(
                "mma.sync.aligned.m16n8k16.row.col.f32.f16.f16.f32 "
                "{%0,%1,%2,%3}, {%4,%5,%6,%7}, {%8,%9}, {%0,%1,%2,%3};"
                : "+f"(c0), "+f"(c1), "+f"(c2), "+f"(c3)
                : "r"(a[ks][0]), "r"(a[ks][1]), "r"(a[ks][2]), "r"(a[ks][3]),
                  "r"(b[nt][ks][0]), "r"(b[nt][ks][1]));
        }
        const int col = (nt << 3) + (tig << 1);
        *(__half2*)(zs + (wbase + gid) * 72 + col)     = __floats2half2_rn(c0, c1);
        *(__half2*)(zs + (wbase + gid + 8) * 72 + col) = __floats2half2_rn(c2, c3);
    }
    __syncthreads();

    {
        uint4* zg = ((uint4*)g_zh) + ((size_t)row0 << 3);
#pragma unroll
        for (int it = 0; it < 4; it++) {
            int idx = tid + (it << 8);
            int rl = idx >> 3, c = idx & 7;
            zg[idx] = ((const uint4*)(zs + rl * 72))[c];
        }
    }
}

// ---------------------------------------------------------------------------
// K234 (fused, 16 agents/block, full MMA utilization): 128 blocks x 256
// threads — one wave, every block resident.
// Phase 1: all 16 agents x 20 steps of feat gathered into smF (warp w owns
//          agents w and w+8; two t's interleaved -> 4-way MLP).
// Phase 2: per step ONE concatenated MMA with ALL 16 rows live
//          (rows 0-7 = agents 0-7, rows 8-15 = agents 8-15); gate-aligned
//          columns so thread (gid,tig) holds all 4 gates of BOTH agent gid
//          (c0,c1) and agent gid+8 (d2,d3) in registers; update in-register
//          for 2 agents x 2 channels; h ping-pong; ONE barrier per step.
// ---------------------------------------------------------------------------
__global__ __launch_bounds__(256) void k234_lstm(const int* __restrict__ A,
                                                 const float* __restrict__ conv_b,
                                                 const float* __restrict__ w_ih,
                                                 const float* __restrict__ w_hh,
                                                 const float* __restrict__ b_ih,
                                                 const float* __restrict__ b_hh,
                                                 float* __restrict__ out,
                                                 int write_states) {
    __shared__ __half smF[TT * 16 * 72];   // feat, 320 rows x 72 (45 KB)
    __shared__ __half smH[2][16 * 72];     // h ping-pong, 16 agents

    const int tid = threadIdx.x;
    const int wid = tid >> 5;        // 0..7
    const int lane = tid & 31;
    const int gid = lane >> 2;       // 0..7
    const int tig = lane & 3;        // 0..3
    const int ab = blockIdx.x << 4;  // agent base (16 per block)
    const int chb = (wid << 3) + (tig << 1);  // this thread's 2 channels

    // ---- B fragments, gate-aligned: nt = gate, cols nt*64 + wid*8 + ... ----
    unsigned b[4][8][2];
    float2 biasv[4];
#pragma unroll
    for (int nt = 0; nt < 4; nt++) {
        const int n0 = (nt << 6) + (wid << 3) + gid;
#pragma unroll
        for (int ks = 0; ks < 8; ks++) {
            const float* wr = (ks < 4 ? w_ih : w_hh) + n0 * 64;
            const int k0 = ((ks & 3) << 4) + (tig << 1);
            float2 lo = *(const float2*)(wr + k0);
            float2 hi = *(const float2*)(wr + k0 + 8);
            __half2 p0 = __floats2half2_rn(lo.x, lo.y);
            __half2 p1 = __floats2half2_rn(hi.x, hi.y);
            b[nt][ks][0] = *(unsigned*)&p0;
            b[nt][ks][1] = *(unsigned*)&p1;
        }
        const int col = (nt << 6) + chb;
        biasv[nt].x = b_ih[col] + b_hh[col];
        biasv[nt].y = b_ih[col + 1] + b_hh[col + 1];
    }

    // zero both h buffers
    for (int e = tid; e < 16 * 72; e += 256) {
        smH[0][e] = __float2half(0.f);
        smH[1][e] = __float2half(0.f);
    }

    const float2 cb = ((const float2*)conv_b)[lane];

    // ---- Phase 1: gather all feat; warp owns agents wid and wid+8,
    //      two t's interleaved -> 4 gathers in flight ----
    const int ag0 = ab + wid;
    const int ag1 = ab + wid + 8;
    for (int j = 0; j < TT; j += 2) {
        const int rA0 = (j << 11) + ag0;
        const int rA1 = (j << 11) + ag1;
        const int rB0 = ((j + 1) << 11) + ag0;
        const int rB1 = ((j + 1) << 11) + ag1;
        const int nbA0 = A[(rA0 << 5) + lane];
        const int nbA1 = A[(rA1 << 5) + lane];
        const int nbB0 = A[(rB0 << 5) + lane];
        const int nbB1 = A[(rB1 << 5) + lane];
        __half2 mA0 = __float2half2_rn(-60000.f);
        __half2 mA1 = mA0, mB0 = mA0, mB1 = mA0;
#pragma unroll
        for (int k = 0; k < KK; k++) {
            int a0 = __shfl_sync(0xffffffffu, nbA0, k);
            int a1 = __shfl_sync(0xffffffffu, nbA1, k);
            int b0 = __shfl_sync(0xffffffffu, nbB0, k);
            int b1 = __shfl_sync(0xffffffffu, nbB1, k);
            mA0 = __hmax2(mA0, __ldg(&g_zh[(((j << 11) + a0) << 5) + lane]));
            mA1 = __hmax2(mA1, __ldg(&g_zh[(((j << 11) + a1) << 5) + lane]));
            mB0 = __hmax2(mB0, __ldg(&g_zh[((((j + 1) << 11) + b0) << 5) + lane]));
            mB1 = __hmax2(mB1, __ldg(&g_zh[((((j + 1) << 11) + b1) << 5) + lane]));
        }
        float2 fA0 = __half22float2(mA0), zA0 = __half22float2(g_zh[(rA0 << 5) + lane]);
        float2 fA1 = __half22float2(mA1), zA1 = __half22float2(g_zh[(rA1 << 5) + lane]);
        float2 fB0 = __half22float2(mB0), zB0 = __half22float2(g_zh[(rB0 << 5) + lane]);
        float2 fB1 = __half22float2(mB1), zB1 = __half22float2(g_zh[(rB1 << 5) + lane]);
        *(__half2*)(smF + ((j << 4) + wid) * 72 + (lane << 1)) =
            __floats2half2_rn(fA0.x - zA0.x + cb.x, fA0.y - zA0.y + cb.y);
        *(__half2*)(smF + ((j << 4) + wid + 8) * 72 + (lane << 1)) =
            __floats2half2_rn(fA1.x - zA1.x + cb.x, fA1.y - zA1.y + cb.y);
        *(__half2*)(smF + (((j + 1) << 4) + wid) * 72 + (lane << 1)) =
            __floats2half2_rn(fB0.x - zB0.x + cb.x, fB0.y - zB0.y + cb.y);
        *(__half2*)(smF + (((j + 1) << 4) + wid + 8) * 72 + (lane << 1)) =
            __floats2half2_rn(fB1.x - zB1.x + cb.x, fB1.y - zB1.y + cb.y);
    }
    __syncthreads();

    float2 c2a = make_float2(0.f, 0.f), c2b = make_float2(0.f, 0.f);
    float2 hla = make_float2(0.f, 0.f), hlb = make_float2(0.f, 0.f);

    for (int t = 0; t < TT; t++) {
        const __half* hb = smH[t & 1];
        const __half* fb = smF + (t << 4) * 72;

        // ---- A fragments: feat (ks 0-3) + h (ks 4-7); all 16 rows live ----
        unsigned afr[8][4];
#pragma unroll
        for (int ks = 0; ks < 4; ks++) {
            const int col = (ks << 4) + (tig << 1);
            afr[ks][0] = *(const unsigned*)(fb + gid * 72 + col);
            afr[ks][1] = *(const unsigned*)(fb + (gid + 8) * 72 + col);
            afr[ks][2] = *(const unsigned*)(fb + gid * 72 + col + 8);
            afr[ks][3] = *(const unsigned*)(fb + (gid + 8) * 72 + col + 8);
        }
#pragma unroll
        for (int ks = 4; ks < 8; ks++) {
            const int col = ((ks - 4) << 4) + (tig << 1);
            afr[ks][0] = *(const unsigned*)(hb + gid * 72 + col);
            afr[ks][1] = *(const unsigned*)(hb + (gid + 8) * 72 + col);
            afr[ks][2] = *(const unsigned*)(hb + gid * 72 + col + 8);
            afr[ks][3] = *(const unsigned*)(hb + (gid + 8) * 72 + col + 8);
        }

        // ---- gate-aligned MMAs: nt = gate; c0,c1 -> agent gid,
        //      d2,d3 -> agent gid+8 ----
        float gA[4][2], gB[4][2];
#pragma unroll
        for (int nt = 0; nt < 4; nt++) {
            float c0 = 0.f, c1 = 0.f, d2 = 0.f, d3 = 0.f;
#pragma unroll
            for (int ks = 0; ks < 8; ks++) {
                asm volatile(
                    "mma.sync.aligned.m16n8k16.row.col.f32.f16.f16.f32 "
                    "{%0,%1,%2,%3}, {%4,%5,%6,%7}, {%8,%9}, {%0,%1,%2,%3};"
                    : "+f"(c0), "+f"(c1), "+f"(d2), "+f"(d3)
                    : "r"(afr[ks][0]), "r"(afr[ks][1]), "r"(afr[ks][2]), "r"(afr[ks][3]),
                      "r"(b[nt][ks][0]), "r"(b[nt][ks][1]));
            }
            gA[nt][0] = c0 + biasv[nt].x;
            gA[nt][1] = c1 + biasv[nt].y;
            gB[nt][0] = d2 + biasv[nt].x;
            gB[nt][1] = d3 + biasv[nt].y;
        }

        // ---- in-register update: agent gid ----
        c2a.x = sigf(gA[1][0]) * c2a.x + sigf(gA[0][0]) * tanhf_fast(gA[2][0]);
        c2a.y = sigf(gA[1][1]) * c2a.y + sigf(gA[0][1]) * tanhf_fast(gA[2][1]);
        float2 h2a;
        h2a.x = sigf(gA[3][0]) * tanhf_fast(c2a.x);
        h2a.y = sigf(gA[3][1]) * tanhf_fast(c2a.y);
        hla = h2a;

        // ---- agent gid+8 ----
        c2b.x = sigf(gB[1][0]) * c2b.x + sigf(gB[0][0]) * tanhf_fast(gB[2][0]);
        c2b.y = sigf(gB[1][1]) * c2b.y + sigf(gB[0][1]) * tanhf_fast(gB[2][1]);
        float2 h2b;
        h2b.x = sigf(gB[3][0]) * tanhf_fast(c2b.x);
        h2b.y = sigf(gB[3][1]) * tanhf_fast(c2b.y);
        hlb = h2b;

        __half* hn = smH[(t + 1) & 1];
        *(__half2*)(hn + gid * 72 + chb)       = __floats2half2_rn(h2a.x, h2a.y);
        *(__half2*)(hn + (gid + 8) * 72 + chb) = __floats2half2_rn(h2b.x, h2b.y);
        *(float2*)(out + (((size_t)(ab + gid) * TT + t) << 6) + chb)     = h2a;
        *(float2*)(out + (((size_t)(ab + gid + 8) * TT + t) << 6) + chb) = h2b;

        __syncthreads();   // h(t) visible before step t+1 reads
    }

    if (write_states) {
        float2* hn = (float2*)(out + (size_t)NN * TT * OO);
        float2* cn = (float2*)(out + (size_t)NN * TT * OO + (size_t)NN * OO);
        hn[((ab + gid) << 5) + (chb >> 1)]     = hla;
        cn[((ab + gid) << 5) + (chb >> 1)]     = c2a;
        hn[((ab + gid + 8) << 5) + (chb >> 1)] = hlb;
        cn[((ab + gid + 8) << 5) + (chb >> 1)] = c2b;
    }
}

// ---------------------------------------------------------------------------
extern "C" void kernel_launch(void* const* d_in, const int* in_sizes, int n_in,
                              void* d_out, int out_size) {
    const float* x      = (const float*)d_in[0];
    const int*   A      = (const int*)  d_in[1];
    const float* conv_w = (const float*)d_in[2];
    const float* conv_b = (const float*)d_in[3];
    const float* w_ih   = (const float*)d_in[4];
    const float* w_hh   = (const float*)d_in[5];
    const float* b_ih   = (const float*)d_in[6];
    const float* b_hh   = (const float*)d_in[7];
    float* out = (float*)d_out;

    const long main_sz = (long)NN * TT * OO;
    int write_states = (out_size >= main_sz + 2L * NN * OO) ? 1 : 0;

    k1_project<<<(TT * NN) / 128, 256>>>(x, conv_w);
    k234_lstm<<<NN / 16, 256>>>(A, conv_b, w_ih, w_hh, b_ih, b_hh, out, write_states);
}

// round 17
// speedup vs baseline: 1.0444x; 1.0444x over previous
#include <cuda_runtime.h>
#include <cuda_fp16.h>
#include <math.h>

#define NN 2048
#define TT 20
#define KK 32
#define CC 32
#define OO 64

// Scratch (static device globals; no runtime allocation)
__device__ __half2 g_zh[TT * NN * (OO / 2)];   // z fp16 (only intermediate)
__device__ unsigned g_cnt = 0;                 // grid-barrier arrivals
__device__ volatile unsigned g_gen = 0;        // grid-barrier generation

// NaN-safe fast sigmoid / tanh (rel err ~1e-7, 2 MUFU each)
__device__ __forceinline__ float sigf(float x) {
    return __fdividef(1.0f, 1.0f + __expf(-x));
}
__device__ __forceinline__ float tanhf_fast(float x) {
    return 1.0f - __fdividef(2.0f, __expf(2.0f * x) + 1.0f);
}

// ---------------------------------------------------------------------------
// Fused kernel: 256 blocks x 256 threads, __launch_bounds__(256,2) ->
// 2 blocks/SM, all 256 blocks co-resident (<= 296 capacity) => the software
// grid barrier below cannot deadlock.
// Phase A: z projection (tensor-core, block owns 160 rows) -> g_zh (global),
//          then threadfence + grid barrier (generation counter).
// Phase B: pre-gather all feat (8 agents x 20 steps) into smem.
// Phase C: R15 recurrence: per step one concatenated MMA
//          gates = [feat|h] @ [w_ih|w_hh]^T (gate-aligned columns, all gates
//          in registers), in-register LSTM update, h ping-pong; out staged in
//          f32 smem and flushed every 4 steps as coalesced float4 stores.
// ---------------------------------------------------------------------------
__global__ __launch_bounds__(256, 2) void fused_all(
    const float* __restrict__ x, const float* __restrict__ conv_w,
    const int* __restrict__ A, const float* __restrict__ conv_b,
    const float* __restrict__ w_ih, const float* __restrict__ w_hh,
    const float* __restrict__ b_ih, const float* __restrict__ b_hh,
    float* __restrict__ out, int write_states)
{
    // pool layout (35840 B total):
    //   [0, 23040)      smF: feat 160 rows x 72 halves   (phase A: zs staging)
    //   [23040, 27648)  smH: h ping-pong 2 x 16 x 72     (phase A: xs part 1)
    //   [27648, 35840)  smOut: 8 agents x 4 t x 64 f32   (phase A: xs part 2)
    __shared__ __align__(16) char pool[35840];
    __half* smF  = (__half*)pool;
    __half* smH0 = (__half*)(pool + 23040);
    float*  smOut = (float*)(pool + 27648);

    const int tid = threadIdx.x;
    const int wid = tid >> 5;        // 0..7
    const int lane = tid & 31;
    const int gid = lane >> 2;       // 0..7
    const int tig = lane & 3;        // 0..3
    const int ab = blockIdx.x << 3;  // agent base (8 per block)
    const int chb = (wid << 3) + (tig << 1);  // thread's 2 channels

    // ===================== Phase A: z projection =====================
    {
        __half* zs = (__half*)pool;            // 160 x 72
        __half* xs = (__half*)(pool + 23040);  // 160 x 40 (12800 B)
        const int row0 = blockIdx.x * 160;     // rows = t*N + n

        unsigned bw[8][2][2];
#pragma unroll
        for (int nt = 0; nt < 8; nt++) {
            const int n0 = (nt << 3) + gid;
            const float* wr = conv_w + n0 * 32;
#pragma unroll
            for (int ks = 0; ks < 2; ks++) {
                const int k0 = (ks << 4) + (tig << 1);
                float2 lo = *(const float2*)(wr + k0);
                float2 hi = *(const float2*)(wr + k0 + 8);
                __half2 p0 = __floats2half2_rn(lo.x, lo.y);
                __half2 p1 = __floats2half2_rn(hi.x, hi.y);
                bw[nt][ks][0] = *(unsigned*)&p0;
                bw[nt][ks][1] = *(unsigned*)&p1;
            }
        }
        {
            const float4* x4 = (const float4*)x;
#pragma unroll
            for (int it = 0; it < 5; it++) {
                int idx = tid + (it << 8);       // 1280 float4 total
                int rl = idx >> 3, c4 = idx & 7;
                int row = row0 + rl;
                int t = row >> 11, n = row & (NN - 1);
                float4 v = x4[((n * TT + t) << 3) + c4];
                *(__half2*)(xs + rl * 40 + (c4 << 2))     = __floats2half2_rn(v.x, v.y);
                *(__half2*)(xs + rl * 40 + (c4 << 2) + 2) = __floats2half2_rn(v.z, v.w);
            }
        }
        __syncthreads();

        // 10 m16 tiles of 16 rows; warp w does tiles w (and 8+w for w<2)
        for (int tile = wid; tile < 10; tile += 8) {
            const int rbase = tile << 4;
            unsigned a1[2][4];
#pragma unroll
            for (int ks = 0; ks < 2; ks++) {
                const int col = (ks << 4) + (tig << 1);
                a1[ks][0] = *(const unsigned*)(xs + (rbase + gid) * 40 + col);
                a1[ks][1] = *(const unsigned*)(xs + (rbase + gid + 8) * 40 + col);
                a1[ks][2] = *(const unsigned*)(xs + (rbase + gid) * 40 + col + 8);
                a1[ks][3] = *(const unsigned*)(xs + (rbase + gid + 8) * 40 + col + 8);
            }
#pragma unroll
            for (int nt = 0; nt < 8; nt++) {
                float c0 = 0.f, c1 = 0.f, c2 = 0.f, c3 = 0.f;
#pragma unroll
                for (int ks = 0; ks < 2; ks++) {
                    asm volatile(
                        "mma.sync.aligned.m16n8k16.row.col.f32.f16.f16.f32 "
                        "{%0,%1,%2,%3}, {%4,%5,%6,%7}, {%8,%9}, {%0,%1,%2,%3};"
                        : "+f"(c0), "+f"(c1), "+f"(c2), "+f"(c3)
                        : "r"(a1[ks][0]), "r"(a1[ks][1]), "r"(a1[ks][2]), "r"(a1[ks][3]),
                          "r"(bw[nt][ks][0]), "r"(bw[nt][ks][1]));
                }
                const int col = (nt << 3) + (tig << 1);
                *(__half2*)(zs + (rbase + gid) * 72 + col)     = __floats2half2_rn(c0, c1);
                *(__half2*)(zs + (rbase + gid + 8) * 72 + col) = __floats2half2_rn(c2, c3);
            }
        }
        __syncthreads();

        // coalesced writeback: 160 rows x 128 B
        uint4* zg = ((uint4*)g_zh) + (size_t)row0 * 8;
#pragma unroll
        for (int it = 0; it < 5; it++) {
            int idx = tid + (it << 8);
            int rl = idx >> 3, c = idx & 7;
            zg[idx] = ((const uint4*)(zs + rl * 72))[c];
        }
        __threadfence();
        __syncthreads();

        // ---- software grid barrier (generation counter) ----
        if (tid == 0) {
            unsigned gen = g_gen;
            if (atomicAdd(&g_cnt, 1u) == (unsigned)(gridDim.x - 1)) {
                g_cnt = 0;
                __threadfence();
                g_gen = gen + 1u;
            } else {
                while (g_gen == gen) { }
            }
        }
        __syncthreads();
    }

    // ===================== Phase B: pre-gather feat =====================
    for (int e = tid; e < 2 * 16 * 72; e += 256) smH0[e] = __float2half(0.f);

    const float2 cb = ((const float2*)conv_b)[lane];
    const int agent = ab + wid;
    for (int j = 0; j < TT; j += 2) {
        const int row0 = (j << 11) + agent;
        const int row1 = ((j + 1) << 11) + agent;
        const int nb0 = A[(row0 << 5) + lane];
        const int nb1 = A[(row1 << 5) + lane];
        __half2 m0 = __float2half2_rn(-60000.f);
        __half2 m1 = m0;
#pragma unroll
        for (int k = 0; k < KK; k++) {
            int r0 = __shfl_sync(0xffffffffu, nb0, k);
            int r1 = __shfl_sync(0xffffffffu, nb1, k);
            m0 = __hmax2(m0, __ldg(&g_zh[(((j << 11) + r0) << 5) + lane]));
            m1 = __hmax2(m1, __ldg(&g_zh[((((j + 1) << 11) + r1) << 5) + lane]));
        }
        float2 mf0 = __half22float2(m0), zc0 = __half22float2(g_zh[(row0 << 5) + lane]);
        float2 mf1 = __half22float2(m1), zc1 = __half22float2(g_zh[(row1 << 5) + lane]);
        *(__half2*)(smF + ((j << 3) + wid) * 72 + (lane << 1)) =
            __floats2half2_rn(mf0.x - zc0.x + cb.x, mf0.y - zc0.y + cb.y);
        *(__half2*)(smF + (((j + 1) << 3) + wid) * 72 + (lane << 1)) =
            __floats2half2_rn(mf1.x - zc1.x + cb.x, mf1.y - zc1.y + cb.y);
    }

    // B fragments, gate-aligned: nt = gate, cols nt*64 + wid*8 + ...
    unsigned b[4][8][2];
    float2 biasv[4];
#pragma unroll
    for (int nt = 0; nt < 4; nt++) {
        const int n0 = (nt << 6) + (wid << 3) + gid;
#pragma unroll
        for (int ks = 0; ks < 8; ks++) {
            const float* wr = (ks < 4 ? w_ih : w_hh) + n0 * 64;
            const int k0 = ((ks & 3) << 4) + (tig << 1);
            float2 lo = *(const float2*)(wr + k0);
            float2 hi = *(const float2*)(wr + k0 + 8);
            __half2 p0 = __floats2half2_rn(lo.x, lo.y);
            __half2 p1 = __floats2half2_rn(hi.x, hi.y);
            b[nt][ks][0] = *(unsigned*)&p0;
            b[nt][ks][1] = *(unsigned*)&p1;
        }
        const int col = (nt << 6) + chb;
        biasv[nt].x = b_ih[col] + b_hh[col];
        biasv[nt].y = b_ih[col + 1] + b_hh[col + 1];
    }
    __syncthreads();   // feat + zeroed smH visible

    // ===================== Phase C: recurrence =====================
    float2 c2r = make_float2(0.f, 0.f);
    float2 h_last = make_float2(0.f, 0.f);

    for (int t = 0; t < TT; t++) {
        const __half* hb = smH0 + (t & 1) * (16 * 72);
        const __half* fb = smF + (t << 3) * 72;

        unsigned afr[8][4];
#pragma unroll
        for (int ks = 0; ks < 4; ks++) {
            const int col = (ks << 4) + (tig << 1);
            afr[ks][0] = *(const unsigned*)(fb + gid * 72 + col);
            afr[ks][1] = *(const unsigned*)(hb + (gid + 8) * 72 + col);      // zeros
            afr[ks][2] = *(const unsigned*)(fb + gid * 72 + col + 8);
            afr[ks][3] = *(const unsigned*)(hb + (gid + 8) * 72 + col + 8);  // zeros
        }
#pragma unroll
        for (int ks = 4; ks < 8; ks++) {
            const int col = ((ks - 4) << 4) + (tig << 1);
            afr[ks][0] = *(const unsigned*)(hb + gid * 72 + col);
            afr[ks][1] = *(const unsigned*)(hb + (gid + 8) * 72 + col);      // zeros
            afr[ks][2] = *(const unsigned*)(hb + gid * 72 + col + 8);
            afr[ks][3] = *(const unsigned*)(hb + (gid + 8) * 72 + col + 8);  // zeros
        }

        float gA[4][2];
#pragma unroll
        for (int nt = 0; nt < 4; nt++) {
            float c0 = 0.f, c1 = 0.f, d2 = 0.f, d3 = 0.f;
#pragma unroll
            for (int ks = 0; ks < 8; ks++) {
                asm volatile(
                    "mma.sync.aligned.m16n8k16.row.col.f32.f16.f16.f32 "
                    "{%0,%1,%2,%3}, {%4,%5,%6,%7}, {%8,%9}, {%0,%1,%2,%3};"
                    : "+f"(c0), "+f"(c1), "+f"(d2), "+f"(d3)
                    : "r"(afr[ks][0]), "r"(afr[ks][1]), "r"(afr[ks][2]), "r"(afr[ks][3]),
                      "r"(b[nt][ks][0]), "r"(b[nt][ks][1]));
            }
            gA[nt][0] = c0 + biasv[nt].x;
            gA[nt][1] = c1 + biasv[nt].y;
        }

        // in-register update: agent gid, channels chb, chb+1
        c2r.x = sigf(gA[1][0]) * c2r.x + sigf(gA[0][0]) * tanhf_fast(gA[2][0]);
        c2r.y = sigf(gA[1][1]) * c2r.y + sigf(gA[0][1]) * tanhf_fast(gA[2][1]);
        float2 h2;
        h2.x = sigf(gA[3][0]) * tanhf_fast(c2r.x);
        h2.y = sigf(gA[3][1]) * tanhf_fast(c2r.y);
        h_last = h2;

        *(__half2*)(smH0 + ((t + 1) & 1) * (16 * 72) + gid * 72 + chb) =
            __floats2half2_rn(h2.x, h2.y);
        *(float2*)(smOut + (((gid << 2) + (t & 3)) << 6) + chb) = h2;  // f32 staging
        __syncthreads();   // h(t)+smOut visible

        if ((t & 3) == 3) {   // flush 4 staged steps, coalesced
            const int t0 = t - 3;
#pragma unroll
            for (int k2 = 0; k2 < 2; k2++) {
                int idx = tid + (k2 << 8);     // 512 float4 total
                int r = idx >> 4;              // 0..31: agent r>>2, tl r&3
                int a = r >> 2, tl = r & 3;
                int c4 = idx & 15;
                *(float4*)(out + (((size_t)(ab + a) * TT + t0 + tl) << 6) + (c4 << 2)) =
                    ((const float4*)smOut)[idx];
            }
            __syncthreads();   // smOut reusable
        }
    }

    if (write_states) {
        float2* hn = (float2*)(out + (size_t)NN * TT * OO);
        float2* cn = (float2*)(out + (size_t)NN * TT * OO + (size_t)NN * OO);
        hn[((ab + gid) << 5) + (chb >> 1)] = h_last;
        cn[((ab + gid) << 5) + (chb >> 1)] = c2r;
    }
}

// ---------------------------------------------------------------------------
extern "C" void kernel_launch(void* const* d_in, const int* in_sizes, int n_in,
                              void* d_out, int out_size) {
    const float* x      = (const float*)d_in[0];
    const int*   A      = (const int*)  d_in[1];
    const float* conv_w = (const float*)d_in[2];
    const float* conv_b = (const float*)d_in[3];
    const float* w_ih   = (const float*)d_in[4];
    const float* w_hh   = (const float*)d_in[5];
    const float* b_ih   = (const float*)d_in[6];
    const float* b_hh   = (const float*)d_in[7];
    float* out = (float*)d_out;

    const long main_sz = (long)NN * TT * OO;
    int write_states = (out_size >= main_sz + 2L * NN * OO) ? 1 : 0;

    fused_all<<<NN / 8, 256>>>(x, conv_w, A, conv_b, w_ih, w_hh, b_ih, b_hh,
                               out, write_states);
}